// round 4
// baseline (speedup 1.0000x reference)
#include <cuda_runtime.h>
#include <math.h>

// OnlineNeuron: T=4 two-compartment SNN recurrence, elementwise, f32.
// Pure HBM-streaming: 256 MB read + 256 MB write, irreducible.
// Round-4: Blackwell 256-bit global accesses (ld/st.global.v8.f32).
// One 8-float tile per thread, 4 front-batched LDG.256 (one per timestep),
// 4 back-batched STG.256. MLP=4 at 256b granularity == R3's byte-MLP with
// R2's register footprint.

#define T_STEPS 4

__device__ __forceinline__ float sigmoidf_(float v) {
    return 1.0f / (1.0f + expf(-v));
}

struct F8 { float v[8]; };

__device__ __forceinline__ F8 ldg256(const float* p) {
    F8 d;
    asm volatile("ld.global.v8.f32 {%0,%1,%2,%3,%4,%5,%6,%7}, [%8];"
        : "=f"(d.v[0]), "=f"(d.v[1]), "=f"(d.v[2]), "=f"(d.v[3]),
          "=f"(d.v[4]), "=f"(d.v[5]), "=f"(d.v[6]), "=f"(d.v[7])
        : "l"(p));
    return d;
}

__device__ __forceinline__ void stg256(float* p, const F8& d) {
    asm volatile("st.global.v8.f32 [%0], {%1,%2,%3,%4,%5,%6,%7,%8};"
        :: "l"(p),
           "f"(d.v[0]), "f"(d.v[1]), "f"(d.v[2]), "f"(d.v[3]),
           "f"(d.v[4]), "f"(d.v[5]), "f"(d.v[6]), "f"(d.v[7])
        : "memory");
}

__global__ __launch_bounds__(256)
void online_neuron_kernel(const float* __restrict__ x,
                          const float* __restrict__ alpha1,
                          const float* __restrict__ beta1,
                          const float* __restrict__ alpha2,
                          const float* __restrict__ beta2,
                          float* __restrict__ out,
                          int n8)   // 8-float chunks per timestep slab
{
    const int i = blockIdx.x * blockDim.x + threadIdx.x;
    if (i >= n8) return;

    const long long elem_stride = (long long)n8 * 8;  // floats between slabs
    const float* xp = x + (long long)i * 8;
    float*       op = out + (long long)i * 8;

    // ---- Front-batched loads: 4 independent LDG.256 in flight ----
    F8 xt[T_STEPS];
    #pragma unroll
    for (int t = 0; t < T_STEPS; t++)
        xt[t] = ldg256(xp + (long long)t * elem_stride);

    const float a1 = sigmoidf_(__ldg(alpha1)) - 0.5f;
    const float b1 = sigmoidf_(__ldg(beta1))  - 0.5f;
    const float a2 = sigmoidf_(__ldg(alpha2)) + 0.5f;
    const float b2 = sigmoidf_(__ldg(beta2))  + 0.5f;

    float vd[8], vs[8];
    #pragma unroll
    for (int j = 0; j < 8; j++) { vd[j] = 0.0f; vs[j] = 0.5f; }

    F8 o[T_STEPS];

    #pragma unroll
    for (int t = 0; t < T_STEPS; t++) {
        #pragma unroll
        for (int j = 0; j < 8; j++) {
            vd[j] = a1 * vd[j] + b1 * vs[j] + xt[t].v[j];
            vs[j] = a2 * vs[j] + b2 * vd[j];
            float sp = (vs[j] >= 1.0f) ? 1.0f : 0.0f;
            o[t].v[j] = sp;
            vs[j] -= sp;
        }
    }

    // ---- Back-batched stores: 4 STG.256 ----
    #pragma unroll
    for (int t = 0; t < T_STEPS; t++)
        stg256(op + (long long)t * elem_stride, o[t]);
}

extern "C" void kernel_launch(void* const* d_in, const int* in_sizes, int n_in,
                              void* d_out, int out_size)
{
    const float* x      = (const float*)d_in[0];
    const float* alpha1 = (const float*)d_in[1];
    const float* beta1  = (const float*)d_in[2];
    const float* alpha2 = (const float*)d_in[3];
    const float* beta2  = (const float*)d_in[4];
    float* out = (float*)d_out;

    const int n_total = in_sizes[0];          // 512*128*32*32 = 67,108,864
    const int n_slab  = n_total / T_STEPS;    // 16,777,216 floats per slab
    const int n8      = n_slab / 8;           // 2,097,152 8-float chunks

    const int block = 256;
    const int grid  = (n8 + block - 1) / block;   // 8192

    online_neuron_kernel<<<grid, block>>>(
        x, alpha1, beta1, alpha2, beta2, out, n8);
}